// round 2
// baseline (speedup 1.0000x reference)
#include <cuda_runtime.h>
#include <cuda_bf16.h>

// SparseCrop: coords (N,4) int32, feats (N,C=64) float32.
// mask[i] = all(10 <= coords[i, 0:3] < 90)
// out_feats = feats * mask[:, None]
// Output buffer layout (float32): [out_feats (N*C), mask (N)] if out_size permits.

__global__ void sparse_crop_kernel(const int4* __restrict__ coords,
                                   const float4* __restrict__ feats,
                                   float4* __restrict__ out_feats,
                                   float* __restrict__ mask_out,
                                   int n_vec4,          // N * (C/4)
                                   int row_shift,       // log2(C/4)
                                   int row_mask,        // (C/4) - 1
                                   int write_mask)
{
    int idx = blockIdx.x * blockDim.x + threadIdx.x;
    if (idx >= n_vec4) return;

    int row = idx >> row_shift;

    // coords row is 4 int32 = one aligned int4 (16B load, L1/L2 broadcast)
    int4 c = coords[row];
    // 10 <= v < 90  <=>  (unsigned)(v - 10) < 80
    bool m = ((unsigned)(c.x - 10) < 80u) &&
             ((unsigned)(c.y - 10) < 80u) &&
             ((unsigned)(c.z - 10) < 80u);
    float s = m ? 1.0f : 0.0f;

    float4 f = feats[idx];
    f.x *= s; f.y *= s; f.z *= s; f.w *= s;
    out_feats[idx] = f;

    if (write_mask && (idx & row_mask) == 0) {
        mask_out[row] = s;
    }
}

// Fallback for non-power-of-two C/4 (not expected here, but keeps us correct
// if the shape variant differs).
__global__ void sparse_crop_kernel_div(const int4* __restrict__ coords,
                                       const float4* __restrict__ feats,
                                       float4* __restrict__ out_feats,
                                       float* __restrict__ mask_out,
                                       int n_vec4,
                                       int vecs_per_row,
                                       int write_mask)
{
    int idx = blockIdx.x * blockDim.x + threadIdx.x;
    if (idx >= n_vec4) return;

    int row = idx / vecs_per_row;
    int4 c = coords[row];
    bool m = ((unsigned)(c.x - 10) < 80u) &&
             ((unsigned)(c.y - 10) < 80u) &&
             ((unsigned)(c.z - 10) < 80u);
    float s = m ? 1.0f : 0.0f;

    float4 f = feats[idx];
    f.x *= s; f.y *= s; f.z *= s; f.w *= s;
    out_feats[idx] = f;

    if (write_mask && (idx - row * vecs_per_row) == 0) {
        mask_out[row] = s;
    }
}

extern "C" void kernel_launch(void* const* d_in, const int* in_sizes, int n_in,
                              void* d_out, int out_size)
{
    const int* coords = (const int*)d_in[0];     // (N, 4) int32
    const float* feats = (const float*)d_in[1];  // (N, C) float32
    float* out = (float*)d_out;

    int N = in_sizes[0] / 4;
    int C = in_sizes[1] / N;          // 64
    int vecs_per_row = C / 4;         // 16
    int n_vec4 = N * vecs_per_row;

    // mask tail present if the output buffer holds N*C + N elements
    int write_mask = (out_size >= N * C + N) ? 1 : 0;
    float* mask_out = out + (size_t)N * C;

    int threads = 256;
    int blocks = (n_vec4 + threads - 1) / threads;

    bool pow2 = (vecs_per_row & (vecs_per_row - 1)) == 0;
    if (pow2) {
        int shift = 0;
        while ((1 << shift) < vecs_per_row) shift++;
        sparse_crop_kernel<<<blocks, threads>>>(
            (const int4*)coords, (const float4*)feats,
            (float4*)out, mask_out,
            n_vec4, shift, vecs_per_row - 1, write_mask);
    } else {
        sparse_crop_kernel_div<<<blocks, threads>>>(
            (const int4*)coords, (const float4*)feats,
            (float4*)out, mask_out,
            n_vec4, vecs_per_row, write_mask);
    }
}

// round 3
// speedup vs baseline: 1.1130x; 1.1130x over previous
#include <cuda_runtime.h>
#include <cuda_bf16.h>

// SparseCrop: coords (N,4) int32, feats (N,C=64) float32.
// mask[i] = all(10 <= coords[i, 0:3] < 90)   (~51.2% pass rate)
// out_feats = feats * mask[:, None]
// Output layout (float32): [out_feats (N*C), mask (N)].
//
// Key optimization: for masked-out rows the output is exactly zero, so the
// feats read is skipped entirely (predicated LDG fetches no sectors).
// Cuts DRAM read traffic by ~48.8% of the feats volume.

__global__ void sparse_crop_kernel(const int4* __restrict__ coords,
                                   const float4* __restrict__ feats,
                                   float4* __restrict__ out_feats,
                                   float* __restrict__ mask_out,
                                   int n_vec4,          // N * (C/4)
                                   int row_shift,       // log2(C/4)
                                   int row_mask,        // (C/4) - 1
                                   int write_mask)
{
    int idx = blockIdx.x * blockDim.x + threadIdx.x;
    if (idx >= n_vec4) return;

    int row = idx >> row_shift;

    // coords row is one aligned int4 (L1-broadcast among the 16 lanes of a row)
    int4 c = coords[row];
    // 10 <= v < 90  <=>  (unsigned)(v - 10) < 80
    bool m = ((unsigned)(c.x - 10) < 80u) &&
             ((unsigned)(c.y - 10) < 80u) &&
             ((unsigned)(c.z - 10) < 80u);

    float4 f = make_float4(0.f, 0.f, 0.f, 0.f);
    if (m) {
        f = feats[idx];            // predicated load: no DRAM traffic when !m
    }
    __stcs(&out_feats[idx], f);    // streaming store: don't pollute L2

    if (write_mask && (idx & row_mask) == 0) {
        mask_out[row] = m ? 1.0f : 0.0f;
    }
}

// Fallback for non-power-of-two C/4 (shape-variant safety).
__global__ void sparse_crop_kernel_div(const int4* __restrict__ coords,
                                       const float4* __restrict__ feats,
                                       float4* __restrict__ out_feats,
                                       float* __restrict__ mask_out,
                                       int n_vec4,
                                       int vecs_per_row,
                                       int write_mask)
{
    int idx = blockIdx.x * blockDim.x + threadIdx.x;
    if (idx >= n_vec4) return;

    int row = idx / vecs_per_row;
    int4 c = coords[row];
    bool m = ((unsigned)(c.x - 10) < 80u) &&
             ((unsigned)(c.y - 10) < 80u) &&
             ((unsigned)(c.z - 10) < 80u);

    float4 f = make_float4(0.f, 0.f, 0.f, 0.f);
    if (m) {
        f = feats[idx];
    }
    __stcs(&out_feats[idx], f);

    if (write_mask && (idx - row * vecs_per_row) == 0) {
        mask_out[row] = m ? 1.0f : 0.0f;
    }
}

extern "C" void kernel_launch(void* const* d_in, const int* in_sizes, int n_in,
                              void* d_out, int out_size)
{
    const int* coords = (const int*)d_in[0];     // (N, 4) int32
    const float* feats = (const float*)d_in[1];  // (N, C) float32
    float* out = (float*)d_out;

    int N = in_sizes[0] / 4;
    int C = in_sizes[1] / N;          // 64
    int vecs_per_row = C / 4;         // 16
    int n_vec4 = N * vecs_per_row;

    int write_mask = (out_size >= N * C + N) ? 1 : 0;
    float* mask_out = out + (size_t)N * C;

    int threads = 256;
    int blocks = (n_vec4 + threads - 1) / threads;

    bool pow2 = (vecs_per_row & (vecs_per_row - 1)) == 0;
    if (pow2) {
        int shift = 0;
        while ((1 << shift) < vecs_per_row) shift++;
        sparse_crop_kernel<<<blocks, threads>>>(
            (const int4*)coords, (const float4*)feats,
            (float4*)out, mask_out,
            n_vec4, shift, vecs_per_row - 1, write_mask);
    } else {
        sparse_crop_kernel_div<<<blocks, threads>>>(
            (const int4*)coords, (const float4*)feats,
            (float4*)out, mask_out,
            n_vec4, vecs_per_row, write_mask);
    }
}

// round 4
// speedup vs baseline: 1.3307x; 1.1955x over previous
#include <cuda_runtime.h>
#include <cuda_bf16.h>

// SparseCrop: coords (N,4) int32, feats (N,C=64) float32.
// mask[i] = all(10 <= coords[i, 0:3] < 90)   (~51.2% pass rate)
// out_feats = feats * mask[:, None]
// Output layout (float32): [out_feats (N*C), mask (N)].
//
// R3 finding: predicated loads cut traffic but dropped MLP to 1/warp ->
// latency-bound (DRAM 51%). Fix: 4 independent float4 per thread, loads
// batched ahead of stores (MLP_p1=4), block-strided for full coalescing.

#define UNROLL 4

__global__ void sparse_crop_kernel(const int4* __restrict__ coords,
                                   const float4* __restrict__ feats,
                                   float4* __restrict__ out_feats,
                                   float* __restrict__ mask_out,
                                   int n_vec4,          // N * (C/4)
                                   int row_shift,       // log2(C/4)
                                   int row_mask,        // (C/4) - 1
                                   int write_mask)
{
    int base = blockIdx.x * (blockDim.x * UNROLL) + threadIdx.x;

    int   idx[UNROLL];
    bool  ok [UNROLL];
    bool  m  [UNROLL];
    float4 f [UNROLL];

    // Phase 1: masks + batched predicated loads (front-batched for MLP)
    #pragma unroll
    for (int k = 0; k < UNROLL; k++) {
        idx[k] = base + k * blockDim.x;
        ok[k]  = idx[k] < n_vec4;
        m[k]   = false;
        f[k]   = make_float4(0.f, 0.f, 0.f, 0.f);
        if (ok[k]) {
            int row = idx[k] >> row_shift;
            int4 c  = coords[row];
            // 10 <= v < 90  <=>  (unsigned)(v - 10) < 80
            m[k] = ((unsigned)(c.x - 10) < 80u) &&
                   ((unsigned)(c.y - 10) < 80u) &&
                   ((unsigned)(c.z - 10) < 80u);
            if (m[k]) {
                f[k] = feats[idx[k]];   // predicated: no traffic when !m
            }
        }
    }

    // Phase 2: stores (streaming — output is write-once)
    #pragma unroll
    for (int k = 0; k < UNROLL; k++) {
        if (ok[k]) {
            __stcs(&out_feats[idx[k]], f[k]);
            if (write_mask && (idx[k] & row_mask) == 0) {
                mask_out[idx[k] >> row_shift] = m[k] ? 1.0f : 0.0f;
            }
        }
    }
}

// Fallback for non-power-of-two C/4 (shape-variant safety).
__global__ void sparse_crop_kernel_div(const int4* __restrict__ coords,
                                       const float4* __restrict__ feats,
                                       float4* __restrict__ out_feats,
                                       float* __restrict__ mask_out,
                                       int n_vec4,
                                       int vecs_per_row,
                                       int write_mask)
{
    int idx = blockIdx.x * blockDim.x + threadIdx.x;
    if (idx >= n_vec4) return;

    int row = idx / vecs_per_row;
    int4 c = coords[row];
    bool m = ((unsigned)(c.x - 10) < 80u) &&
             ((unsigned)(c.y - 10) < 80u) &&
             ((unsigned)(c.z - 10) < 80u);

    float4 f = make_float4(0.f, 0.f, 0.f, 0.f);
    if (m) {
        f = feats[idx];
    }
    __stcs(&out_feats[idx], f);

    if (write_mask && (idx - row * vecs_per_row) == 0) {
        mask_out[row] = m ? 1.0f : 0.0f;
    }
}

extern "C" void kernel_launch(void* const* d_in, const int* in_sizes, int n_in,
                              void* d_out, int out_size)
{
    const int* coords = (const int*)d_in[0];     // (N, 4) int32
    const float* feats = (const float*)d_in[1];  // (N, C) float32
    float* out = (float*)d_out;

    int N = in_sizes[0] / 4;
    int C = in_sizes[1] / N;          // 64
    int vecs_per_row = C / 4;         // 16
    int n_vec4 = N * vecs_per_row;

    int write_mask = (out_size >= N * C + N) ? 1 : 0;
    float* mask_out = out + (size_t)N * C;

    int threads = 256;

    bool pow2 = (vecs_per_row & (vecs_per_row - 1)) == 0;
    if (pow2) {
        int shift = 0;
        while ((1 << shift) < vecs_per_row) shift++;
        int tile = threads * UNROLL;
        int blocks = (n_vec4 + tile - 1) / tile;
        sparse_crop_kernel<<<blocks, threads>>>(
            (const int4*)coords, (const float4*)feats,
            (float4*)out, mask_out,
            n_vec4, shift, vecs_per_row - 1, write_mask);
    } else {
        int blocks = (n_vec4 + threads - 1) / threads;
        sparse_crop_kernel_div<<<blocks, threads>>>(
            (const int4*)coords, (const float4*)feats,
            (float4*)out, mask_out,
            n_vec4, vecs_per_row, write_mask);
    }
}